// round 11
// baseline (speedup 1.0000x reference)
#include <cuda_runtime.h>
#include <cuda_bf16.h>
#include <cstdint>
#include <cstddef>

#define HID 96
#define G3  288      // 3*H
#define TT  512
#define BB  512
#define II  100
#define BC  8        // batch elements per recurrence CTA
#define MM  (TT * BB)
#define KPU 112      // padded K used by MMA (7 x k16)
#define PBM 128      // proj M tile
#define AST 120      // smem k-stride in halves (conflict-free)

// Scratch: input projections [dir][t*B + b][3H]
__device__ float g_xp[(size_t)2 * MM * G3];
// Pre-split bf16 weights: [dir][term][288][112]
__device__ __nv_bfloat16 g_wb[(size_t)2 * 2 * G3 * KPU];
// Pre-split bf16 inputs: [term][M][112]
__device__ __nv_bfloat16 g_xb[(size_t)2 * MM * KPU];

// ---------- packed fp32x2 helpers ----------
__device__ __forceinline__ unsigned long long pk2(float lo, float hi) {
    unsigned long long r;
    asm("mov.b64 %0, {%1, %2};" : "=l"(r) : "f"(lo), "f"(hi));
    return r;
}
__device__ __forceinline__ void upk2(unsigned long long v, float& lo, float& hi) {
    asm("mov.b64 {%0, %1}, %2;" : "=f"(lo), "=f"(hi) : "l"(v));
}
__device__ __forceinline__ unsigned long long fma2(unsigned long long a,
                                                   unsigned long long b,
                                                   unsigned long long c) {
    unsigned long long d;
    asm("fma.rn.f32x2 %0, %1, %2, %3;" : "=l"(d) : "l"(a), "l"(b), "l"(c));
    return d;
}
__device__ __forceinline__ float sigmoidf_(float x) {
    return __fdividef(1.f, 1.f + __expf(-x));
}
__device__ __forceinline__ float tanhf_(float x) {
    float e = __expf(-2.f * fabsf(x));
    float t = __fdividef(1.f - e, 1.f + e);
    return copysignf(t, x);
}
__device__ __forceinline__ void mma16816(float* c, const uint32_t* a, const uint32_t* b) {
    asm volatile(
        "mma.sync.aligned.m16n8k16.row.col.f32.bf16.bf16.f32 "
        "{%0,%1,%2,%3}, {%4,%5,%6,%7}, {%8,%9}, {%0,%1,%2,%3};"
        : "+f"(c[0]), "+f"(c[1]), "+f"(c[2]), "+f"(c[3])
        : "r"(a[0]), "r"(a[1]), "r"(a[2]), "r"(a[3]), "r"(b[0]), "r"(b[1]));
}

// =====================================================================
// Kernel W: W_ih -> bf16 hi/lo, K padded to 112
// =====================================================================
__global__ void wconv_kernel(const float* __restrict__ wf, const float* __restrict__ wb)
{
    int idx = blockIdx.x * 256 + threadIdx.x;
    if (idx >= 2 * G3 * KPU) return;
    int dir = idx / (G3 * KPU);
    int rem = idx - dir * (G3 * KPU);
    int n = rem / KPU, k = rem - n * KPU;
    const float* w = dir ? wb : wf;
    float v = (k < II) ? w[n * II + k] : 0.f;
    __nv_bfloat16 h = __float2bfloat16(v);
    __nv_bfloat16 l = __float2bfloat16(v - __bfloat162float(h));
    g_wb[((size_t)dir * 2 + 0) * G3 * KPU + rem] = h;
    g_wb[((size_t)dir * 2 + 1) * G3 * KPU + rem] = l;
}

// =====================================================================
// Kernel X: x -> bf16 hi/lo, [term][M][112]
// =====================================================================
__global__ void xconv_kernel(const float* __restrict__ x)
{
    int idx = blockIdx.x * 256 + threadIdx.x;
    if (idx >= MM * KPU) return;
    int r = idx / KPU, k = idx - r * KPU;
    float v = (k < II) ? x[(size_t)r * II + k] : 0.f;
    __nv_bfloat16 h = __float2bfloat16(v);
    __nv_bfloat16 l = __float2bfloat16(v - __bfloat162float(h));
    g_xb[idx] = h;
    g_xb[(size_t)MM * KPU + idx] = l;
}

// =====================================================================
// Kernel A: projection GEMM via mma.sync bf16 (3-term split, fp32 accum)
//   At the legacy-HMMA roofline (~32 cyc/SMSP per m16n8k16) — unchanged.
// =====================================================================
#define SA0 0                      // A hi: 128*120*2 = 30720 B
#define SA1 30720                  // A lo
#define SB0 61440                  // B hi: 96*120*2 = 23040 B
#define SB1 84480                  // B lo
#define SBIAS 107520               // 96 floats
#define SMTOT (107520 + 96 * 4)

__global__ void __launch_bounds__(256) proj_mma_kernel(
    const float* __restrict__ b_ih_f, const float* __restrict__ b_ih_b)
{
    extern __shared__ char smp[];
    const int tid = threadIdx.x, wid = tid >> 5, lid = tid & 31;
    const int dir = blockIdx.z;
    const int ny = blockIdx.y;                 // N-block (3 x 96)
    const size_t row0 = (size_t)blockIdx.x * PBM;
    const float* bias = dir ? b_ih_b : b_ih_f;
    float* bsm = (float*)(smp + SBIAS);

    if (tid < 96) bsm[tid] = bias[ny * 96 + tid];

    // Fill A: 2 terms x 128 rows x 14 uint4 = 3584 copies
    for (int idx = tid; idx < 3584; idx += 256) {
        int term = idx / 1792;
        int rem = idx - term * 1792;
        int r = rem / 14, k8 = (rem - r * 14) * 8;
        uint4 v = *(const uint4*)&g_xb[((size_t)term * MM + row0 + r) * KPU + k8];
        *(uint4*)((__nv_bfloat16*)(smp + (term ? SA1 : SA0)) + r * AST + k8) = v;
    }
    // Fill B: 2 terms x 96 rows x 14 uint4 = 2688 copies
    for (int idx = tid; idx < 2688; idx += 256) {
        int term = idx / 1344;
        int rem = idx - term * 1344;
        int n = rem / 14, k8 = (rem - n * 14) * 8;
        uint4 v = *(const uint4*)&g_wb[(((size_t)dir * 2 + term) * G3 + ny * 96 + n) * KPU + k8];
        *(uint4*)((__nv_bfloat16*)(smp + (term ? SB1 : SB0)) + n * AST + k8) = v;
    }
    __syncthreads();

    const int wm = wid & 3, wn = wid >> 2;
    const int m0 = wm * 32, n0 = wn * 48;
    const int gid = lid >> 2, tig = lid & 3;

    float acc[2][6][4];
#pragma unroll
    for (int i = 0; i < 2; i++)
#pragma unroll
        for (int j = 0; j < 6; j++)
#pragma unroll
            for (int q = 0; q < 4; q++) acc[i][j][q] = 0.f;

#pragma unroll 1
    for (int term = 0; term < 3; term++) {
        const __nv_bfloat16* As = (const __nv_bfloat16*)(smp + (term == 2 ? SA1 : SA0));
        const __nv_bfloat16* Bs = (const __nv_bfloat16*)(smp + (term == 1 ? SB1 : SB0));
#pragma unroll
        for (int ks = 0; ks < 7; ks++) {
            const int kk = ks * 16 + tig * 2;
            uint32_t a[2][4], b[6][2];
#pragma unroll
            for (int i = 0; i < 2; i++) {
                int r = m0 + i * 16 + gid;
                a[i][0] = *(const uint32_t*)&As[r * AST + kk];
                a[i][1] = *(const uint32_t*)&As[(r + 8) * AST + kk];
                a[i][2] = *(const uint32_t*)&As[r * AST + kk + 8];
                a[i][3] = *(const uint32_t*)&As[(r + 8) * AST + kk + 8];
            }
#pragma unroll
            for (int j = 0; j < 6; j++) {
                int n = n0 + j * 8 + gid;
                b[j][0] = *(const uint32_t*)&Bs[n * AST + kk];
                b[j][1] = *(const uint32_t*)&Bs[n * AST + kk + 8];
            }
#pragma unroll
            for (int i = 0; i < 2; i++)
#pragma unroll
                for (int j = 0; j < 6; j++)
                    mma16816(acc[i][j], a[i], b[j]);
        }
    }

    // Epilogue: add bias, write g_xp
#pragma unroll
    for (int i = 0; i < 2; i++) {
        size_t r = row0 + m0 + i * 16 + gid;
        size_t gb0 = ((size_t)dir * MM + r) * G3;
        size_t gb1 = gb0 + 8 * G3;
#pragma unroll
        for (int j = 0; j < 6; j++) {
            int bn = n0 + j * 8 + tig * 2;
            float bz0 = bsm[bn], bz1 = bsm[bn + 1];
            int g = ny * 96 + bn;
            *(float2*)&g_xp[gb0 + g] = make_float2(acc[i][j][0] + bz0, acc[i][j][1] + bz1);
            *(float2*)&g_xp[gb1 + g] = make_float2(acc[i][j][2] + bz0, acc[i][j][3] + bz1);
        }
    }
}

// =====================================================================
// Kernel B: GRU recurrence. CTA = (dir, 8 batch), 1024 threads.
//   Thread (g = tid>>2 in 0..255, q = tid&3) holds 24 W_hh weights in
//   registers; quarter-dots reduced by 2x shfl.bfly. Rows 256..287 are
//   handled by warps 28..31 AFTER the main b-loop, with weights loaded
//   from SMEM each step (short live range -> no spill under 64-reg cap).
// =====================================================================
__global__ void __launch_bounds__(1024, 1) gru_scan_kernel(
    const float* __restrict__ w_hh_f, const float* __restrict__ b_hh_f,
    const float* __restrict__ w_hh_b, const float* __restrict__ b_hh_b,
    float* __restrict__ out)
{
    __shared__ __align__(16) float hs [2][BC][HID];   // 6 KB
    __shared__ __align__(16) float hps[BC][G3];       // 9 KB (final dots)
    __shared__ __align__(16) float swt[32][HID];      // 12 KB tail weights
    __shared__ float bhs[G3];

    const int tid  = threadIdx.x;
    const int dir  = blockIdx.y;
    const int b0   = blockIdx.x * BC;
    const float* whh = dir ? w_hh_b : w_hh_f;
    const float* bhh = dir ? b_hh_b : b_hh_f;

    const int g = tid >> 2;      // 0..255
    const int q = tid & 3;       // 0..3
    const bool tail = (tid >= 896);
    const int g2 = 256 + ((tid - 896) >> 2);   // 256..287 (tail threads)

    // Main 24 weights -> 12 packed f32x2 (resident)
    unsigned long long w2[12];
    {
        const float4* wr = (const float4*)(whh + (size_t)g * HID + q * 24);
#pragma unroll
        for (int j = 0; j < 6; j++) {
            float4 f = wr[j];
            w2[2 * j]     = pk2(f.x, f.y);
            w2[2 * j + 1] = pk2(f.z, f.w);
        }
    }
    // Tail weights (rows 256..287) into SMEM
    for (int i = tid; i < 32 * HID; i += 1024)
        ((float*)swt)[i] = whh[256 * HID + i];
    if (tid < G3) bhs[tid] = bhh[tid];
    for (int i = tid; i < BC * HID; i += 1024) ((float*)hs[0])[i] = 0.f;
    __syncthreads();

    // Phase-2 identity (fixed): unit = (b, j), valid when tid < 768
    const int p2b = tid / HID, p2j = tid - p2b * HID;

    for (int s = 0; s < TT; s++) {
        const int cur = s & 1, nxt = cur ^ 1;
        const int tt = dir ? (TT - 1 - s) : s;

        // Prefetch this step's x_proj (consumed in phase 2, far later)
        float xr = 0.f, xz = 0.f, xn = 0.f;
        if (tid < BC * HID) {
            const float* xpp = g_xp +
                ((size_t)dir * MM + (size_t)tt * BB + (b0 + p2b)) * G3 + p2j;
            xr = xpp[0];
            xz = xpp[96];
            xn = xpp[192];
        }

        // Phase 1 (main): quarter-dots + butterfly -> hps[b][g]
#pragma unroll
        for (int b = 0; b < BC; b++) {
            const ulonglong2* h2 = (const ulonglong2*)(&hs[cur][b][q * 24]);
            ulonglong2 h0 = h2[0], h1 = h2[1], h2v = h2[2];
            ulonglong2 h3 = h2[3], h4 = h2[4], h5 = h2[5];
            unsigned long long a0, a1;
            a0 = fma2(w2[0],  h0.x, 0ull);  a1 = fma2(w2[1],  h0.y, 0ull);
            a0 = fma2(w2[2],  h1.x, a0);    a1 = fma2(w2[3],  h1.y, a1);
            a0 = fma2(w2[4],  h2v.x, a0);   a1 = fma2(w2[5],  h2v.y, a1);
            a0 = fma2(w2[6],  h3.x, a0);    a1 = fma2(w2[7],  h3.y, a1);
            a0 = fma2(w2[8],  h4.x, a0);    a1 = fma2(w2[9],  h4.y, a1);
            a0 = fma2(w2[10], h5.x, a0);    a1 = fma2(w2[11], h5.y, a1);
            float p0, p1, p2, p3;
            upk2(a0, p0, p1); upk2(a1, p2, p3);
            float p = (p0 + p1) + (p2 + p3);
            p += __shfl_xor_sync(0xffffffffu, p, 1);
            p += __shfl_xor_sync(0xffffffffu, p, 2);
            if (q == 0) hps[b][g] = p;
        }

        // Phase 1 (tail, warps 28-31): rows 256..287, weights from SMEM
        // (short register live range; loaded fresh each step)
        if (tail) {
            const ulonglong2* wt = (const ulonglong2*)(&swt[g2 - 256][q * 24]);
            ulonglong2 t0 = wt[0], t1 = wt[1], t2w = wt[2];
            ulonglong2 t3 = wt[3], t4 = wt[4], t5 = wt[5];
#pragma unroll
            for (int b = 0; b < BC; b++) {
                const ulonglong2* h2 = (const ulonglong2*)(&hs[cur][b][q * 24]);
                ulonglong2 h0 = h2[0], h1 = h2[1], h2v = h2[2];
                ulonglong2 h3 = h2[3], h4 = h2[4], h5 = h2[5];
                unsigned long long c0, c1;
                c0 = fma2(t0.x,  h0.x, 0ull);  c1 = fma2(t0.y,  h0.y, 0ull);
                c0 = fma2(t1.x,  h1.x, c0);    c1 = fma2(t1.y,  h1.y, c1);
                c0 = fma2(t2w.x, h2v.x, c0);   c1 = fma2(t2w.y, h2v.y, c1);
                c0 = fma2(t3.x,  h3.x, c0);    c1 = fma2(t3.y,  h3.y, c1);
                c0 = fma2(t4.x,  h4.x, c0);    c1 = fma2(t4.y,  h4.y, c1);
                c0 = fma2(t5.x,  h5.x, c0);    c1 = fma2(t5.y,  h5.y, c1);
                float u0, u1, u2, u3;
                upk2(c0, u0, u1); upk2(c1, u2, u3);
                float pt = (u0 + u1) + (u2 + u3);
                pt += __shfl_xor_sync(0xffffffffu, pt, 1);
                pt += __shfl_xor_sync(0xffffffffu, pt, 2);
                if (q == 0) hps[b][g2] = pt;
            }
        }
        __syncthreads();

        // Phase 2: gates + state update (768 units, single pass)
        if (tid < BC * HID) {
            float hpr = hps[p2b][p2j]       + bhs[p2j];
            float hpz = hps[p2b][p2j + 96]  + bhs[p2j + 96];
            float hpn = hps[p2b][p2j + 192] + bhs[p2j + 192];
            float r = sigmoidf_(xr + hpr);
            float z = sigmoidf_(xz + hpz);
            float n = tanhf_  (xn + r * hpn);
            float hn = (1.f - z) * n + z * hs[cur][p2b][p2j];
            hs[nxt][p2b][p2j] = hn;
            out[((size_t)tt * BB + (b0 + p2b)) * (2 * HID) + dir * HID + p2j] = hn;
        }
        __syncthreads();
    }
}

// =====================================================================
extern "C" void kernel_launch(void* const* d_in, const int* in_sizes, int n_in,
                              void* d_out, int out_size)
{
    const float* x      = (const float*)d_in[0];
    const float* w_ih_f = (const float*)d_in[1];
    const float* w_hh_f = (const float*)d_in[2];
    const float* b_ih_f = (const float*)d_in[3];
    const float* b_hh_f = (const float*)d_in[4];
    const float* w_ih_b = (const float*)d_in[5];
    const float* w_hh_b = (const float*)d_in[6];
    const float* b_ih_b = (const float*)d_in[7];
    const float* b_hh_b = (const float*)d_in[8];
    float* out = (float*)d_out;

    wconv_kernel<<<(2 * G3 * KPU + 255) / 256, 256>>>(w_ih_f, w_ih_b);
    xconv_kernel<<<(MM * KPU + 255) / 256, 256>>>(x);

    cudaFuncSetAttribute(proj_mma_kernel,
                         cudaFuncAttributeMaxDynamicSharedMemorySize, SMTOT);
    dim3 gA(MM / PBM, 3, 2);                 // (2048, 3, 2)
    proj_mma_kernel<<<gA, 256, SMTOT>>>(b_ih_f, b_ih_b);

    dim3 gB(BB / BC, 2);                     // 128 CTAs, one wave
    gru_scan_kernel<<<gB, 1024>>>(w_hh_f, b_hh_f, w_hh_b, b_hh_b, out);
}

// round 13
// speedup vs baseline: 3.7589x; 3.7589x over previous
#include <cuda_runtime.h>
#include <cuda_fp16.h>
#include <cstdint>
#include <cstddef>

#define HID 96
#define G3  288      // 3*H
#define TT  512
#define BB  512
#define II  100
#define BC  8        // batch elements per recurrence CTA
#define MM  (TT * BB)
#define KPU 112      // padded K used by MMA (7 x k16)
#define PBM 128      // proj M tile
#define AST 120      // smem k-stride in halves (conflict-free)

// Scratch: input projections [dir][t*B + b][3H]
__device__ float g_xp[(size_t)2 * MM * G3];
// fp16 weights: [dir][288][112]
__device__ __half g_wb[(size_t)2 * G3 * KPU];
// fp16 split inputs: [term(hi/lo)][M][112]
__device__ __half g_xb[(size_t)2 * MM * KPU];

// ---------- packed fp32x2 helpers ----------
__device__ __forceinline__ unsigned long long pk2(float lo, float hi) {
    unsigned long long r;
    asm("mov.b64 %0, {%1, %2};" : "=l"(r) : "f"(lo), "f"(hi));
    return r;
}
__device__ __forceinline__ void upk2(unsigned long long v, float& lo, float& hi) {
    asm("mov.b64 {%0, %1}, %2;" : "=f"(lo), "=f"(hi) : "l"(v));
}
__device__ __forceinline__ unsigned long long fma2(unsigned long long a,
                                                   unsigned long long b,
                                                   unsigned long long c) {
    unsigned long long d;
    asm("fma.rn.f32x2 %0, %1, %2, %3;" : "=l"(d) : "l"(a), "l"(b), "l"(c));
    return d;
}
__device__ __forceinline__ float sigmoidf_(float x) {
    return __fdividef(1.f, 1.f + __expf(-x));
}
__device__ __forceinline__ float tanhf_(float x) {
    float e = __expf(-2.f * fabsf(x));
    float t = __fdividef(1.f - e, 1.f + e);
    return copysignf(t, x);
}
__device__ __forceinline__ void mma16816(float* c, const uint32_t* a, const uint32_t* b) {
    asm volatile(
        "mma.sync.aligned.m16n8k16.row.col.f32.f16.f16.f32 "
        "{%0,%1,%2,%3}, {%4,%5,%6,%7}, {%8,%9}, {%0,%1,%2,%3};"
        : "+f"(c[0]), "+f"(c[1]), "+f"(c[2]), "+f"(c[3])
        : "r"(a[0]), "r"(a[1]), "r"(a[2]), "r"(a[3]), "r"(b[0]), "r"(b[1]));
}

// =====================================================================
// Kernel W: W_ih -> fp16, K padded to 112
// =====================================================================
__global__ void wconv_kernel(const float* __restrict__ wf, const float* __restrict__ wb)
{
    int idx = blockIdx.x * 256 + threadIdx.x;
    if (idx >= 2 * G3 * KPU) return;
    int dir = idx / (G3 * KPU);
    int rem = idx - dir * (G3 * KPU);
    int n = rem / KPU, k = rem - n * KPU;
    const float* w = dir ? wb : wf;
    float v = (k < II) ? w[n * II + k] : 0.f;
    g_wb[idx] = __float2half(v);
}

// =====================================================================
// Kernel X: x -> fp16 hi/lo split, [term][M][112]
// =====================================================================
__global__ void xconv_kernel(const float* __restrict__ x)
{
    int idx = blockIdx.x * 256 + threadIdx.x;
    if (idx >= MM * KPU) return;
    int r = idx / KPU, k = idx - r * KPU;
    float v = (k < II) ? x[(size_t)r * II + k] : 0.f;
    __half h = __float2half(v);
    __half l = __float2half(v - __half2float(h));
    g_xb[idx] = h;
    g_xb[(size_t)MM * KPU + idx] = l;
}

// =====================================================================
// Kernel A: projection GEMM via mma.sync fp16 (2-term x-split, fp32 accum)
//   CTA: 128 rows x 96 gate-cols, K=112. 8 warps (4m x 2n), warp 32x48.
//   Terms: xh*wh + xl*wh = x*wh (w-quantization error ~1e-4 rel only).
// =====================================================================
#define SA0 0                      // A hi: 128*120*2 = 30720 B
#define SA1 30720                  // A lo
#define SB0 61440                  // B: 96*120*2 = 23040 B
#define SBIAS 84480                // 96 floats
#define SMTOT (84480 + 96 * 4)

__global__ void __launch_bounds__(256) proj_mma_kernel(
    const float* __restrict__ b_ih_f, const float* __restrict__ b_ih_b)
{
    extern __shared__ char smp[];
    const int tid = threadIdx.x, wid = tid >> 5, lid = tid & 31;
    const int dir = blockIdx.z;
    const int ny = blockIdx.y;                 // N-block (3 x 96)
    const size_t row0 = (size_t)blockIdx.x * PBM;
    const float* bias = dir ? b_ih_b : b_ih_f;
    float* bsm = (float*)(smp + SBIAS);

    if (tid < 96) bsm[tid] = bias[ny * 96 + tid];

    // Fill A: 2 terms x 128 rows x 14 uint4 = 3584 copies
    for (int idx = tid; idx < 3584; idx += 256) {
        int term = idx / 1792;
        int rem = idx - term * 1792;
        int r = rem / 14, k8 = (rem - r * 14) * 8;
        uint4 v = *(const uint4*)&g_xb[((size_t)term * MM + row0 + r) * KPU + k8];
        *(uint4*)((__half*)(smp + (term ? SA1 : SA0)) + r * AST + k8) = v;
    }
    // Fill B: 96 rows x 14 uint4 = 1344 copies
    for (int idx = tid; idx < 1344; idx += 256) {
        int n = idx / 14, k8 = (idx - n * 14) * 8;
        uint4 v = *(const uint4*)&g_wb[((size_t)dir * G3 + ny * 96 + n) * KPU + k8];
        *(uint4*)((__half*)(smp + SB0) + n * AST + k8) = v;
    }
    __syncthreads();

    const int wm = wid & 3, wn = wid >> 2;
    const int m0 = wm * 32, n0 = wn * 48;
    const int gid = lid >> 2, tig = lid & 3;

    float acc[2][6][4];
#pragma unroll
    for (int i = 0; i < 2; i++)
#pragma unroll
        for (int j = 0; j < 6; j++)
#pragma unroll
            for (int q = 0; q < 4; q++) acc[i][j][q] = 0.f;

#pragma unroll 1
    for (int term = 0; term < 2; term++) {
        const __half* As = (const __half*)(smp + (term ? SA1 : SA0));
        const __half* Bs = (const __half*)(smp + SB0);
#pragma unroll
        for (int ks = 0; ks < 7; ks++) {
            const int kk = ks * 16 + tig * 2;
            uint32_t a[2][4], b[6][2];
#pragma unroll
            for (int i = 0; i < 2; i++) {
                int r = m0 + i * 16 + gid;
                a[i][0] = *(const uint32_t*)&As[r * AST + kk];
                a[i][1] = *(const uint32_t*)&As[(r + 8) * AST + kk];
                a[i][2] = *(const uint32_t*)&As[r * AST + kk + 8];
                a[i][3] = *(const uint32_t*)&As[(r + 8) * AST + kk + 8];
            }
#pragma unroll
            for (int j = 0; j < 6; j++) {
                int n = n0 + j * 8 + gid;
                b[j][0] = *(const uint32_t*)&Bs[n * AST + kk];
                b[j][1] = *(const uint32_t*)&Bs[n * AST + kk + 8];
            }
#pragma unroll
            for (int i = 0; i < 2; i++)
#pragma unroll
                for (int j = 0; j < 6; j++)
                    mma16816(acc[i][j], a[i], b[j]);
        }
    }

    // Epilogue: add bias, write g_xp
#pragma unroll
    for (int i = 0; i < 2; i++) {
        size_t r = row0 + m0 + i * 16 + gid;
        size_t gb0 = ((size_t)dir * MM + r) * G3;
        size_t gb1 = gb0 + 8 * G3;
#pragma unroll
        for (int j = 0; j < 6; j++) {
            int bn = n0 + j * 8 + tig * 2;
            float bz0 = bsm[bn], bz1 = bsm[bn + 1];
            int g = ny * 96 + bn;
            *(float2*)&g_xp[gb0 + g] = make_float2(acc[i][j][0] + bz0, acc[i][j][1] + bz1);
            *(float2*)&g_xp[gb1 + g] = make_float2(acc[i][j][2] + bz0, acc[i][j][3] + bz1);
        }
    }
}

// =====================================================================
// Kernel B: GRU recurrence — R7 version verbatim (known good, no spills).
//   CTA = (dir, 8 batch), 864 threads; thread (g, third) holds 32 W_hh
//   weights in regs; 27 warps/SM; hps partials in smem; xps staged.
// =====================================================================
__global__ void __launch_bounds__(864, 1) gru_scan_kernel(
    const float* __restrict__ w_hh_f, const float* __restrict__ b_hh_f,
    const float* __restrict__ w_hh_b, const float* __restrict__ b_hh_b,
    float* __restrict__ out)
{
    __shared__ __align__(16) float hs [2][BC][HID];
    __shared__ __align__(16) float hps[3][BC][G3];   // [third][b][g]
    __shared__ __align__(16) float xps[2][BC][G3];
    __shared__ float bhs[G3];

    const int tid  = threadIdx.x;
    const int dir  = blockIdx.y;
    const int b0   = blockIdx.x * BC;
    const float* whh = dir ? w_hh_b : w_hh_f;
    const float* bhh = dir ? b_hh_b : b_hh_f;

    const int g     = tid % G3;   // 0..287
    const int third = tid / G3;   // 0..2

    // 32 weights -> 16 packed f32x2 pairs
    unsigned long long w2[16];
    {
        const float4* wr = (const float4*)(whh + (size_t)g * HID + third * 32);
#pragma unroll
        for (int j = 0; j < 8; j++) {
            float4 f = wr[j];
            w2[2 * j]     = pk2(f.x, f.y);
            w2[2 * j + 1] = pk2(f.z, f.w);
        }
    }
    if (tid < G3) bhs[tid] = bhh[tid];
    for (int i = tid; i < BC * HID; i += 864) ((float*)hs[0])[i] = 0.f;
    if (tid < 576) {
        int tt0 = dir ? (TT - 1) : 0;
        const float4* src = (const float4*)(g_xp +
            ((size_t)dir * MM + (size_t)tt0 * BB + b0) * G3);
        ((float4*)xps[0])[tid] = src[tid];
    }
    __syncthreads();

    for (int s = 0; s < TT; s++) {
        const int cur = s & 1, nxt = cur ^ 1;
        const int tt = dir ? (TT - 1 - s) : s;

        float4 xnext = make_float4(0.f, 0.f, 0.f, 0.f);
        if (tid < 576) {
            int s1  = (s + 1 < TT) ? s + 1 : s;
            int tt1 = dir ? (TT - 1 - s1) : s1;
            const float4* src = (const float4*)(g_xp +
                ((size_t)dir * MM + (size_t)tt1 * BB + b0) * G3);
            xnext = src[tid];
        }

        // Phase 1: third-dot  hps[third][b][g] = W_hh[g, third*32 : +32] . h[b, ...]
#pragma unroll 2
        for (int b = 0; b < BC; b++) {
            const ulonglong2* h2 = (const ulonglong2*)(&hs[cur][b][third * 32]);
            unsigned long long a0 = 0ull, a1 = 0ull, a2 = 0ull, a3 = 0ull;
#pragma unroll
            for (int j = 0; j < 8; j += 2) {
                ulonglong2 ha = h2[j];
                ulonglong2 hb = h2[j + 1];
                a0 = fma2(w2[2 * j],     ha.x, a0);
                a1 = fma2(w2[2 * j + 1], ha.y, a1);
                a2 = fma2(w2[2 * j + 2], hb.x, a2);
                a3 = fma2(w2[2 * j + 3], hb.y, a3);
            }
            float p0, p1, p2, p3, p4, p5, p6, p7;
            upk2(a0, p0, p1); upk2(a1, p2, p3);
            upk2(a2, p4, p5); upk2(a3, p6, p7);
            hps[third][b][g] = ((p0 + p1) + (p2 + p3)) + ((p4 + p5) + (p6 + p7));
        }
        __syncthreads();

        // Phase 2: gates + state update (768 units, single pass)
        if (tid < BC * HID) {
            int b = tid / HID, j = tid - b * HID;
            float hpr = hps[0][b][j]       + hps[1][b][j]       + hps[2][b][j]       + bhs[j];
            float hpz = hps[0][b][j + 96]  + hps[1][b][j + 96]  + hps[2][b][j + 96]  + bhs[j + 96];
            float hpn = hps[0][b][j + 192] + hps[1][b][j + 192] + hps[2][b][j + 192] + bhs[j + 192];
            float r = sigmoidf_(xps[cur][b][j]       + hpr);
            float z = sigmoidf_(xps[cur][b][j + 96]  + hpz);
            float n = tanhf_  (xps[cur][b][j + 192] + r * hpn);
            float hn = (1.f - z) * n + z * hs[cur][b][j];
            hs[nxt][b][j] = hn;
            out[((size_t)tt * BB + (b0 + b)) * (2 * HID) + dir * HID + j] = hn;
        }
        if (tid < 576) ((float4*)xps[nxt])[tid] = xnext;
        __syncthreads();
    }
}

// =====================================================================
extern "C" void kernel_launch(void* const* d_in, const int* in_sizes, int n_in,
                              void* d_out, int out_size)
{
    const float* x      = (const float*)d_in[0];
    const float* w_ih_f = (const float*)d_in[1];
    const float* w_hh_f = (const float*)d_in[2];
    const float* b_ih_f = (const float*)d_in[3];
    const float* b_hh_f = (const float*)d_in[4];
    const float* w_ih_b = (const float*)d_in[5];
    const float* w_hh_b = (const float*)d_in[6];
    const float* b_ih_b = (const float*)d_in[7];
    const float* b_hh_b = (const float*)d_in[8];
    float* out = (float*)d_out;

    wconv_kernel<<<(2 * G3 * KPU + 255) / 256, 256>>>(w_ih_f, w_ih_b);
    xconv_kernel<<<(MM * KPU + 255) / 256, 256>>>(x);

    cudaFuncSetAttribute(proj_mma_kernel,
                         cudaFuncAttributeMaxDynamicSharedMemorySize, SMTOT);
    dim3 gA(MM / PBM, 3, 2);                 // (2048, 3, 2)
    proj_mma_kernel<<<gA, 256, SMTOT>>>(b_ih_f, b_ih_b);

    dim3 gB(BB / BC, 2);                     // 128 CTAs, one wave
    gru_scan_kernel<<<gB, 864>>>(w_hh_f, b_hh_f, w_hh_b, b_hh_b, out);
}

// round 14
// speedup vs baseline: 6.6081x; 1.7580x over previous
#include <cuda_runtime.h>
#include <cuda_fp16.h>
#include <cstdint>
#include <cstddef>

#define HID 96
#define G3  288      // 3*H
#define TT  512
#define BB  512
#define II  100
#define BC  8        // batch elements per recurrence CTA
#define MM  (TT * BB)
#define KPU 112      // padded K used by MMA (7 x k16)
#define PBM 128      // proj M tile
#define AST 120      // smem k-stride in halves (conflict-free)

// Scratch: input projections [dir][t*B + b][3H]
__device__ float g_xp[(size_t)2 * MM * G3];
// fp16 weights: [dir][288][112]
__device__ __half g_wb[(size_t)2 * G3 * KPU];
// fp16 split inputs: [term(hi/lo)][M][112]
__device__ __half g_xb[(size_t)2 * MM * KPU];

// ---------- packed fp32x2 helpers ----------
__device__ __forceinline__ unsigned long long pk2(float lo, float hi) {
    unsigned long long r;
    asm("mov.b64 %0, {%1, %2};" : "=l"(r) : "f"(lo), "f"(hi));
    return r;
}
__device__ __forceinline__ void upk2(unsigned long long v, float& lo, float& hi) {
    asm("mov.b64 {%0, %1}, %2;" : "=f"(lo), "=f"(hi) : "l"(v));
}
__device__ __forceinline__ unsigned long long fma2(unsigned long long a,
                                                   unsigned long long b,
                                                   unsigned long long c) {
    unsigned long long d;
    asm("fma.rn.f32x2 %0, %1, %2, %3;" : "=l"(d) : "l"(a), "l"(b), "l"(c));
    return d;
}
__device__ __forceinline__ float sigmoidf_(float x) {
    return __fdividef(1.f, 1.f + __expf(-x));
}
__device__ __forceinline__ float tanhf_(float x) {
    float e = __expf(-2.f * fabsf(x));
    float t = __fdividef(1.f - e, 1.f + e);
    return copysignf(t, x);
}
__device__ __forceinline__ void mma16816(float* c, const uint32_t* a, const uint32_t* b) {
    asm volatile(
        "mma.sync.aligned.m16n8k16.row.col.f32.f16.f16.f32 "
        "{%0,%1,%2,%3}, {%4,%5,%6,%7}, {%8,%9}, {%0,%1,%2,%3};"
        : "+f"(c[0]), "+f"(c[1]), "+f"(c[2]), "+f"(c[3])
        : "r"(a[0]), "r"(a[1]), "r"(a[2]), "r"(a[3]), "r"(b[0]), "r"(b[1]));
}

// =====================================================================
// Kernel W: W_ih -> fp16, K padded to 112
// =====================================================================
__global__ void wconv_kernel(const float* __restrict__ wf, const float* __restrict__ wb)
{
    int idx = blockIdx.x * 256 + threadIdx.x;
    if (idx >= 2 * G3 * KPU) return;
    int dir = idx / (G3 * KPU);
    int rem = idx - dir * (G3 * KPU);
    int n = rem / KPU, k = rem - n * KPU;
    const float* w = dir ? wb : wf;
    float v = (k < II) ? w[n * II + k] : 0.f;
    g_wb[idx] = __float2half(v);
}

// =====================================================================
// Kernel X: x -> fp16 hi/lo split, [term][M][112]
// =====================================================================
__global__ void xconv_kernel(const float* __restrict__ x)
{
    int idx = blockIdx.x * 256 + threadIdx.x;
    if (idx >= MM * KPU) return;
    int r = idx / KPU, k = idx - r * KPU;
    float v = (k < II) ? x[(size_t)r * II + k] : 0.f;
    __half h = __float2half(v);
    __half l = __float2half(v - __half2float(h));
    g_xb[idx] = h;
    g_xb[(size_t)MM * KPU + idx] = l;
}

// =====================================================================
// Kernel A: projection GEMM via mma.sync fp16 (2-term x-split, fp32 accum)
//   CTA: 128 rows x 96 gate-cols, K=112. 8 warps (4m x 2n), warp 32x48.
// =====================================================================
#define SA0 0                      // A hi: 128*120*2 = 30720 B
#define SA1 30720                  // A lo
#define SB0 61440                  // B: 96*120*2 = 23040 B
#define SBIAS 84480                // 96 floats
#define SMTOT (84480 + 96 * 4)

__global__ void __launch_bounds__(256) proj_mma_kernel(
    const float* __restrict__ b_ih_f, const float* __restrict__ b_ih_b)
{
    extern __shared__ char smp[];
    const int tid = threadIdx.x, wid = tid >> 5, lid = tid & 31;
    const int dir = blockIdx.z;
    const int ny = blockIdx.y;                 // N-block (3 x 96)
    const size_t row0 = (size_t)blockIdx.x * PBM;
    const float* bias = dir ? b_ih_b : b_ih_f;
    float* bsm = (float*)(smp + SBIAS);

    if (tid < 96) bsm[tid] = bias[ny * 96 + tid];

    // Fill A: 2 terms x 128 rows x 14 uint4 = 3584 copies
    for (int idx = tid; idx < 3584; idx += 256) {
        int term = idx / 1792;
        int rem = idx - term * 1792;
        int r = rem / 14, k8 = (rem - r * 14) * 8;
        uint4 v = *(const uint4*)&g_xb[((size_t)term * MM + row0 + r) * KPU + k8];
        *(uint4*)((__half*)(smp + (term ? SA1 : SA0)) + r * AST + k8) = v;
    }
    // Fill B: 96 rows x 14 uint4 = 1344 copies
    for (int idx = tid; idx < 1344; idx += 256) {
        int n = idx / 14, k8 = (idx - n * 14) * 8;
        uint4 v = *(const uint4*)&g_wb[((size_t)dir * G3 + ny * 96 + n) * KPU + k8];
        *(uint4*)((__half*)(smp + SB0) + n * AST + k8) = v;
    }
    __syncthreads();

    const int wm = wid & 3, wn = wid >> 2;
    const int m0 = wm * 32, n0 = wn * 48;
    const int gid = lid >> 2, tig = lid & 3;

    float acc[2][6][4];
#pragma unroll
    for (int i = 0; i < 2; i++)
#pragma unroll
        for (int j = 0; j < 6; j++)
#pragma unroll
            for (int q = 0; q < 4; q++) acc[i][j][q] = 0.f;

#pragma unroll 1
    for (int term = 0; term < 2; term++) {
        const __half* As = (const __half*)(smp + (term ? SA1 : SA0));
        const __half* Bs = (const __half*)(smp + SB0);
#pragma unroll
        for (int ks = 0; ks < 7; ks++) {
            const int kk = ks * 16 + tig * 2;
            uint32_t a[2][4], b[6][2];
#pragma unroll
            for (int i = 0; i < 2; i++) {
                int r = m0 + i * 16 + gid;
                a[i][0] = *(const uint32_t*)&As[r * AST + kk];
                a[i][1] = *(const uint32_t*)&As[(r + 8) * AST + kk];
                a[i][2] = *(const uint32_t*)&As[r * AST + kk + 8];
                a[i][3] = *(const uint32_t*)&As[(r + 8) * AST + kk + 8];
            }
#pragma unroll
            for (int j = 0; j < 6; j++) {
                int n = n0 + j * 8 + gid;
                b[j][0] = *(const uint32_t*)&Bs[n * AST + kk];
                b[j][1] = *(const uint32_t*)&Bs[n * AST + kk + 8];
            }
#pragma unroll
            for (int i = 0; i < 2; i++)
#pragma unroll
                for (int j = 0; j < 6; j++)
                    mma16816(acc[i][j], a[i], b[j]);
        }
    }

    // Epilogue: add bias, write g_xp
#pragma unroll
    for (int i = 0; i < 2; i++) {
        size_t r = row0 + m0 + i * 16 + gid;
        size_t gb0 = ((size_t)dir * MM + r) * G3;
        size_t gb1 = gb0 + 8 * G3;
#pragma unroll
        for (int j = 0; j < 6; j++) {
            int bn = n0 + j * 8 + tig * 2;
            float bz0 = bsm[bn], bz1 = bsm[bn + 1];
            int g = ny * 96 + bn;
            *(float2*)&g_xp[gb0 + g] = make_float2(acc[i][j][0] + bz0, acc[i][j][1] + bz1);
            *(float2*)&g_xp[gb1 + g] = make_float2(acc[i][j][2] + bz0, acc[i][j][3] + bz1);
        }
    }
}

// =====================================================================
// Kernel B: GRU recurrence (R7 structure + direct HBM x_proj prefetch).
//   CTA = (dir, 8 batch), 864 threads; thread (g, third) holds 32 W_hh
//   weights in regs. Phase-2 threads (tid<768) prefetch their 3 x_proj
//   floats from HBM at step top (no xps smem staging).
// =====================================================================
__global__ void __launch_bounds__(864, 1) gru_scan_kernel(
    const float* __restrict__ w_hh_f, const float* __restrict__ b_hh_f,
    const float* __restrict__ w_hh_b, const float* __restrict__ b_hh_b,
    float* __restrict__ out)
{
    __shared__ __align__(16) float hs [2][BC][HID];
    __shared__ __align__(16) float hps[3][BC][G3];   // [third][b][g]
    __shared__ float bhs[G3];

    const int tid  = threadIdx.x;
    const int dir  = blockIdx.y;
    const int b0   = blockIdx.x * BC;
    const float* whh = dir ? w_hh_b : w_hh_f;
    const float* bhh = dir ? b_hh_b : b_hh_f;

    const int g     = tid % G3;   // 0..287
    const int third = tid / G3;   // 0..2

    // 32 weights -> 16 packed f32x2 pairs
    unsigned long long w2[16];
    {
        const float4* wr = (const float4*)(whh + (size_t)g * HID + third * 32);
#pragma unroll
        for (int j = 0; j < 8; j++) {
            float4 f = wr[j];
            w2[2 * j]     = pk2(f.x, f.y);
            w2[2 * j + 1] = pk2(f.z, f.w);
        }
    }
    if (tid < G3) bhs[tid] = bhh[tid];
    for (int i = tid; i < BC * HID; i += 864) ((float*)hs[0])[i] = 0.f;
    __syncthreads();

    // Phase-2 identity (fixed): unit = (b, j), valid when tid < 768
    const int p2b = tid / HID, p2j = tid - p2b * HID;

    for (int s = 0; s < TT; s++) {
        const int cur = s & 1, nxt = cur ^ 1;
        const int tt = dir ? (TT - 1 - s) : s;

        // Prefetch this step's x_proj from HBM (consumed in phase 2)
        float xr = 0.f, xz = 0.f, xn = 0.f;
        if (tid < BC * HID) {
            const float* xpp = g_xp +
                ((size_t)dir * MM + (size_t)tt * BB + (b0 + p2b)) * G3 + p2j;
            xr = xpp[0];
            xz = xpp[96];
            xn = xpp[192];
        }

        // Phase 1: third-dot  hps[third][b][g] = W_hh[g, third*32 : +32] . h[b, ...]
#pragma unroll 2
        for (int b = 0; b < BC; b++) {
            const ulonglong2* h2 = (const ulonglong2*)(&hs[cur][b][third * 32]);
            unsigned long long a0 = 0ull, a1 = 0ull, a2 = 0ull, a3 = 0ull;
#pragma unroll
            for (int j = 0; j < 8; j += 2) {
                ulonglong2 ha = h2[j];
                ulonglong2 hb = h2[j + 1];
                a0 = fma2(w2[2 * j],     ha.x, a0);
                a1 = fma2(w2[2 * j + 1], ha.y, a1);
                a2 = fma2(w2[2 * j + 2], hb.x, a2);
                a3 = fma2(w2[2 * j + 3], hb.y, a3);
            }
            float p0, p1, p2, p3, p4, p5, p6, p7;
            upk2(a0, p0, p1); upk2(a1, p2, p3);
            upk2(a2, p4, p5); upk2(a3, p6, p7);
            hps[third][b][g] = ((p0 + p1) + (p2 + p3)) + ((p4 + p5) + (p6 + p7));
        }
        __syncthreads();

        // Phase 2: gates + state update (768 units, single pass)
        if (tid < BC * HID) {
            float hpr = hps[0][p2b][p2j]       + hps[1][p2b][p2j]       + hps[2][p2b][p2j]       + bhs[p2j];
            float hpz = hps[0][p2b][p2j + 96]  + hps[1][p2b][p2j + 96]  + hps[2][p2b][p2j + 96]  + bhs[p2j + 96];
            float hpn = hps[0][p2b][p2j + 192] + hps[1][p2b][p2j + 192] + hps[2][p2b][p2j + 192] + bhs[p2j + 192];
            float r = sigmoidf_(xr + hpr);
            float z = sigmoidf_(xz + hpz);
            float n = tanhf_  (xn + r * hpn);
            float hn = (1.f - z) * n + z * hs[cur][p2b][p2j];
            hs[nxt][p2b][p2j] = hn;
            out[((size_t)tt * BB + (b0 + p2b)) * (2 * HID) + dir * HID + p2j] = hn;
        }
        __syncthreads();
    }
}

// =====================================================================
extern "C" void kernel_launch(void* const* d_in, const int* in_sizes, int n_in,
                              void* d_out, int out_size)
{
    const float* x      = (const float*)d_in[0];
    const float* w_ih_f = (const float*)d_in[1];
    const float* w_hh_f = (const float*)d_in[2];
    const float* b_ih_f = (const float*)d_in[3];
    const float* b_hh_f = (const float*)d_in[4];
    const float* w_ih_b = (const float*)d_in[5];
    const float* w_hh_b = (const float*)d_in[6];
    const float* b_ih_b = (const float*)d_in[7];
    const float* b_hh_b = (const float*)d_in[8];
    float* out = (float*)d_out;

    wconv_kernel<<<(2 * G3 * KPU + 255) / 256, 256>>>(w_ih_f, w_ih_b);
    xconv_kernel<<<(MM * KPU + 255) / 256, 256>>>(x);

    cudaFuncSetAttribute(proj_mma_kernel,
                         cudaFuncAttributeMaxDynamicSharedMemorySize, SMTOT);
    dim3 gA(MM / PBM, 3, 2);                 // (2048, 3, 2)
    proj_mma_kernel<<<gA, 256, SMTOT>>>(b_ih_f, b_ih_b);

    dim3 gB(BB / BC, 2);                     // 128 CTAs, one wave
    gru_scan_kernel<<<gB, 864>>>(w_hh_f, b_hh_f, w_hh_b, b_hh_b, out);
}